// round 1
// baseline (speedup 1.0000x reference)
#include <cuda_runtime.h>
#include <cstdint>

#define TOK   8192
#define HDIM  1024
#define FDIM  4096
#define NE    8

// ---------------- scratch (static device globals; no runtime allocation) ----
__device__ int   g_counts[NE];
__device__ int   g_offsets[NE + 1];
__device__ int   g_cursor[NE];
__device__ int   g_topk_i[TOK * 2];
__device__ float g_topk_w[TOK * 2];
__device__ int   g_list[TOK * 2];                       // pair ids grouped by expert
__device__ float g_hid[(size_t)TOK * 2 * FDIM];         // 268 MB: gelu(x@w1+b1) per pair
__device__ float g_contrib[(size_t)TOK * 2 * HDIM];     // 67 MB: weighted expert output per pair

// ---------------- helpers ---------------------------------------------------
__device__ __forceinline__ uint32_t f2tf32(float f) {
    uint32_t r;
    asm("cvt.rna.tf32.f32 %0, %1;" : "=r"(r) : "f"(f));
    return r;
}

__device__ __forceinline__ void mma_tf32(float* d, const uint32_t* a, const uint32_t* b) {
    asm volatile(
        "mma.sync.aligned.m16n8k8.row.col.f32.tf32.tf32.f32 "
        "{%0,%1,%2,%3}, {%4,%5,%6,%7}, {%8,%9}, {%0,%1,%2,%3};"
        : "+f"(d[0]), "+f"(d[1]), "+f"(d[2]), "+f"(d[3])
        : "r"(a[0]), "r"(a[1]), "r"(a[2]), "r"(a[3]), "r"(b[0]), "r"(b[1]));
}

__device__ __forceinline__ float gelu_exact(float v) {
    return 0.5f * v * (1.0f + erff(v * 0.70710678118654752f));
}

// ---------------- setup kernels ---------------------------------------------
__global__ void reset_kernel() {
    if (threadIdx.x < NE) g_counts[threadIdx.x] = 0;
}

// one warp per token: logits over 8 experts, softmax, top-2
__global__ void router_kernel(const float* __restrict__ x, const float* __restrict__ rw) {
    __shared__ float srw[NE * HDIM];
    int tid = threadIdx.x;
    for (int i = tid; i < NE * HDIM; i += 256) srw[i] = rw[i];
    __syncthreads();
    int warp = tid >> 5, lane = tid & 31;
    int t = blockIdx.x * 8 + warp;
    if (t >= TOK) return;
    const float* xr = x + (size_t)t * HDIM;
    float acc[NE];
#pragma unroll
    for (int e = 0; e < NE; e++) acc[e] = 0.0f;
    for (int h = lane; h < HDIM; h += 32) {
        float xv = xr[h];
#pragma unroll
        for (int e = 0; e < NE; e++) acc[e] += xv * srw[e * HDIM + h];
    }
#pragma unroll
    for (int off = 16; off > 0; off >>= 1) {
#pragma unroll
        for (int e = 0; e < NE; e++) acc[e] += __shfl_xor_sync(0xffffffffu, acc[e], off);
    }
    if (lane == 0) {
        float mx = acc[0];
#pragma unroll
        for (int e = 1; e < NE; e++) mx = fmaxf(mx, acc[e]);
        float p[NE], s = 0.0f;
#pragma unroll
        for (int e = 0; e < NE; e++) { p[e] = expf(acc[e] - mx); s += p[e]; }
        float inv = 1.0f / s;
#pragma unroll
        for (int e = 0; e < NE; e++) p[e] *= inv;
        int i1 = 0;
#pragma unroll
        for (int e = 1; e < NE; e++) if (p[e] > p[i1]) i1 = e;
        int i2 = (i1 == 0) ? 1 : 0;
#pragma unroll
        for (int e = 0; e < NE; e++) if (e != i1 && p[e] > p[i2]) i2 = e;
        g_topk_i[t * 2 + 0] = i1; g_topk_w[t * 2 + 0] = p[i1];
        g_topk_i[t * 2 + 1] = i2; g_topk_w[t * 2 + 1] = p[i2];
        atomicAdd(&g_counts[i1], 1);
        atomicAdd(&g_counts[i2], 1);
    }
}

__global__ void scan_kernel() {
    if (threadIdx.x == 0) {
        int o = 0;
        g_offsets[0] = 0;
        for (int e = 0; e < NE; e++) {
            g_cursor[e] = o;
            o += g_counts[e];
            g_offsets[e + 1] = o;
        }
    }
}

__global__ void scatter_kernel() {
    int t = blockIdx.x * 256 + threadIdx.x;
    if (t < TOK) {
#pragma unroll
        for (int s = 0; s < 2; s++) {
            int e = g_topk_i[t * 2 + s];
            int pos = atomicAdd(&g_cursor[e], 1);
            g_list[pos] = t * 2 + s;
        }
    }
}

// ---------------- grouped GEMM ----------------------------------------------
// Block tile 128x128x32, 256 threads, 2(M)x4(N) warps, warp tile 64x32 via
// m16n8k8 tf32 mma.sync. FFN1: A = gathered x rows -> gelu -> g_hid.
// FFN2: A = g_hid rows -> weighted -> g_contrib (per pair id, deterministic).
template <int KDIM_, int NDIM_, bool FFN1>
__global__ __launch_bounds__(256, 1) void moe_gemm(const float* __restrict__ x,
                                                   const float* __restrict__ W,
                                                   const float* __restrict__ bias) {
    constexpr int BM = 128, BK = 32;
    constexpr int ASTRIDE = 36;   // 128 rows x (32+4) floats: conflict-free frag loads
    constexpr int BSTRIDE = 136;  // 32 rows x (128+8) floats
    __shared__ float As[128 * ASTRIDE];
    __shared__ float Bs[32 * BSTRIDE];

    int tid = threadIdx.x;
    int e = blockIdx.y >> 6;
    int rt = blockIdx.y & 63;
    int seg0 = g_offsets[e], seg1 = g_offsets[e + 1];
    int row0 = seg0 + rt * BM;
    if (row0 >= seg1) return;
    int n0 = blockIdx.x * 128;

    int warp = tid >> 5, lane = tid & 31;
    int wm = warp & 1, wn = warp >> 1;
    int group = lane >> 2, quad = lane & 3;

    // A tile load: 2 threads per row, 16 floats each
    int arow = tid >> 1;
    int acol = (tid & 1) * 16;
    int gidx = row0 + arow;
    bool avalid = gidx < seg1;
    const float* abase;
    if (FFN1) {
        int pair = avalid ? g_list[gidx] : 0;
        abase = x + (size_t)(pair >> 1) * KDIM_;
    } else {
        abase = g_hid + (size_t)(avalid ? gidx : row0) * KDIM_;
    }
    // B tile load: 8 threads per row of 128, 16 floats each
    int brow = tid >> 3;
    int bcol = (tid & 7) * 16;
    const float* wbase = W + (size_t)e * KDIM_ * NDIM_ + (size_t)brow * NDIM_ + n0 + bcol;

    float acc[4][4][4];
#pragma unroll
    for (int mi = 0; mi < 4; mi++)
#pragma unroll
        for (int ni = 0; ni < 4; ni++)
#pragma unroll
            for (int d = 0; d < 4; d++) acc[mi][ni][d] = 0.0f;

    for (int k0 = 0; k0 < KDIM_; k0 += BK) {
        float4 ar[4], br[4];
        if (avalid) {
            const float* ap = abase + k0 + acol;
#pragma unroll
            for (int i = 0; i < 4; i++) ar[i] = *(const float4*)(ap + i * 4);
        } else {
#pragma unroll
            for (int i = 0; i < 4; i++) ar[i] = make_float4(0.f, 0.f, 0.f, 0.f);
        }
        const float* bp = wbase + (size_t)k0 * NDIM_;
#pragma unroll
        for (int i = 0; i < 4; i++) br[i] = *(const float4*)(bp + i * 4);

        __syncthreads();
        float* asp = As + arow * ASTRIDE + acol;
#pragma unroll
        for (int i = 0; i < 4; i++) {
            asp[i * 4 + 0] = __uint_as_float(f2tf32(ar[i].x));
            asp[i * 4 + 1] = __uint_as_float(f2tf32(ar[i].y));
            asp[i * 4 + 2] = __uint_as_float(f2tf32(ar[i].z));
            asp[i * 4 + 3] = __uint_as_float(f2tf32(ar[i].w));
        }
        float* bsp = Bs + brow * BSTRIDE + bcol;
#pragma unroll
        for (int i = 0; i < 4; i++) {
            bsp[i * 4 + 0] = __uint_as_float(f2tf32(br[i].x));
            bsp[i * 4 + 1] = __uint_as_float(f2tf32(br[i].y));
            bsp[i * 4 + 2] = __uint_as_float(f2tf32(br[i].z));
            bsp[i * 4 + 3] = __uint_as_float(f2tf32(br[i].w));
        }
        __syncthreads();

#pragma unroll
        for (int ks = 0; ks < 4; ks++) {
            int kk = ks * 8;
            uint32_t af[4][4];
#pragma unroll
            for (int mi = 0; mi < 4; mi++) {
                const float* a0 = As + (wm * 64 + mi * 16 + group) * ASTRIDE + kk + quad;
                af[mi][0] = __float_as_uint(a0[0]);
                af[mi][1] = __float_as_uint(a0[8 * ASTRIDE]);
                af[mi][2] = __float_as_uint(a0[4]);
                af[mi][3] = __float_as_uint(a0[8 * ASTRIDE + 4]);
            }
            uint32_t bf[4][2];
#pragma unroll
            for (int ni = 0; ni < 4; ni++) {
                const float* b0 = Bs + (kk + quad) * BSTRIDE + wn * 32 + ni * 8 + group;
                bf[ni][0] = __float_as_uint(b0[0]);
                bf[ni][1] = __float_as_uint(b0[4 * BSTRIDE]);
            }
#pragma unroll
            for (int mi = 0; mi < 4; mi++)
#pragma unroll
                for (int ni = 0; ni < 4; ni++) mma_tf32(acc[mi][ni], af[mi], bf[ni]);
        }
    }

    // epilogue
#pragma unroll
    for (int mi = 0; mi < 4; mi++) {
#pragma unroll
        for (int half = 0; half < 2; half++) {
            int grow = row0 + wm * 64 + mi * 16 + group + half * 8;
            if (grow < seg1) {
                if (FFN1) {
#pragma unroll
                    for (int ni = 0; ni < 4; ni++) {
                        int col = n0 + wn * 32 + ni * 8 + quad * 2;
                        float v0 = acc[mi][ni][half * 2 + 0] + bias[(size_t)e * NDIM_ + col];
                        float v1 = acc[mi][ni][half * 2 + 1] + bias[(size_t)e * NDIM_ + col + 1];
                        v0 = gelu_exact(v0);
                        v1 = gelu_exact(v1);
                        *(float2*)(g_hid + (size_t)grow * NDIM_ + col) = make_float2(v0, v1);
                    }
                } else {
                    int pair = g_list[grow];
                    float wgt = g_topk_w[pair];
#pragma unroll
                    for (int ni = 0; ni < 4; ni++) {
                        int col = n0 + wn * 32 + ni * 8 + quad * 2;
                        float v0 = (acc[mi][ni][half * 2 + 0] + bias[(size_t)e * NDIM_ + col]) * wgt;
                        float v1 = (acc[mi][ni][half * 2 + 1] + bias[(size_t)e * NDIM_ + col + 1]) * wgt;
                        *(float2*)(g_contrib + (size_t)pair * NDIM_ + col) = make_float2(v0, v1);
                    }
                }
            }
        }
    }
}

// ---------------- combine ----------------------------------------------------
__global__ void combine_kernel(float* __restrict__ out) {
    constexpr int H4 = HDIM / 4;
    size_t i = (size_t)blockIdx.x * blockDim.x + threadIdx.x;
    if (i < (size_t)TOK * H4) {
        size_t t = i / H4, h4 = i % H4;
        const float4* c = (const float4*)g_contrib;
        float4 a = c[(t * 2) * H4 + h4];
        float4 b = c[(t * 2 + 1) * H4 + h4];
        float4 o = make_float4(a.x + b.x, a.y + b.y, a.z + b.z, a.w + b.w);
        ((float4*)out)[i] = o;
    }
}

// ---------------- launch ------------------------------------------------------
extern "C" void kernel_launch(void* const* d_in, const int* in_sizes, int n_in,
                              void* d_out, int out_size) {
    const float* x  = (const float*)d_in[0];
    const float* rw = (const float*)d_in[1];
    const float* w1 = (const float*)d_in[2];
    const float* b1 = (const float*)d_in[3];
    const float* w2 = (const float*)d_in[4];
    const float* b2 = (const float*)d_in[5];
    float* out = (float*)d_out;

    reset_kernel<<<1, 32>>>();
    router_kernel<<<TOK / 8, 256>>>(x, rw);
    scan_kernel<<<1, 32>>>();
    scatter_kernel<<<TOK / 256, 256>>>();
    moe_gemm<HDIM, FDIM, true ><<<dim3(FDIM / 128, NE * 64), 256>>>(x, w1, b1);
    moe_gemm<FDIM, HDIM, false><<<dim3(HDIM / 128, NE * 64), 256>>>(x, w2, b2);
    combine_kernel<<<(TOK * HDIM / 4) / 256, 256>>>(out);
}

// round 2
// speedup vs baseline: 1.3866x; 1.3866x over previous
#include <cuda_runtime.h>
#include <cstdint>

#define TOK   8192
#define HDIM  1024
#define FDIM  4096
#define NE    8

// ---------------- scratch (static device globals; no runtime allocation) ----
__device__ int   g_counts[NE];
__device__ int   g_offsets[NE + 1];
__device__ int   g_cursor[NE];
__device__ int   g_topk_i[TOK * 2];
__device__ float g_topk_w[TOK * 2];
__device__ int   g_list[TOK * 2];                       // pair ids grouped by expert
__device__ float g_hid[(size_t)TOK * 2 * FDIM];         // gelu(x@w1+b1) per pair
__device__ float g_contrib[(size_t)TOK * 2 * HDIM];     // weighted expert output per pair

// ---------------- helpers ---------------------------------------------------
__device__ __forceinline__ uint32_t f2tf32(float f) {
    uint32_t r;
    asm("cvt.rna.tf32.f32 %0, %1;" : "=r"(r) : "f"(f));
    return r;
}

__device__ __forceinline__ void mma_tf32(float* d, const uint32_t* a, const uint32_t* b) {
    asm volatile(
        "mma.sync.aligned.m16n8k8.row.col.f32.tf32.tf32.f32 "
        "{%0,%1,%2,%3}, {%4,%5,%6,%7}, {%8,%9}, {%0,%1,%2,%3};"
        : "+f"(d[0]), "+f"(d[1]), "+f"(d[2]), "+f"(d[3])
        : "r"(a[0]), "r"(a[1]), "r"(a[2]), "r"(a[3]), "r"(b[0]), "r"(b[1]));
}

__device__ __forceinline__ void cp16(uint32_t dst, const void* src, int bytes) {
    asm volatile("cp.async.cg.shared.global [%0], [%1], 16, %2;"
                 :: "r"(dst), "l"(src), "r"(bytes));
}

__device__ __forceinline__ float gelu_exact(float v) {
    return 0.5f * v * (1.0f + erff(v * 0.70710678118654752f));
}

// ---------------- setup kernels ---------------------------------------------
__global__ void reset_kernel() {
    if (threadIdx.x < NE) g_counts[threadIdx.x] = 0;
}

// one warp per token: logits over 8 experts, softmax, top-2
__global__ void router_kernel(const float* __restrict__ x, const float* __restrict__ rw) {
    __shared__ float srw[NE * HDIM];
    int tid = threadIdx.x;
    for (int i = tid; i < NE * HDIM; i += 256) srw[i] = rw[i];
    __syncthreads();
    int warp = tid >> 5, lane = tid & 31;
    int t = blockIdx.x * 8 + warp;
    if (t >= TOK) return;
    const float* xr = x + (size_t)t * HDIM;
    float acc[NE];
#pragma unroll
    for (int e = 0; e < NE; e++) acc[e] = 0.0f;
    for (int h = lane; h < HDIM; h += 32) {
        float xv = xr[h];
#pragma unroll
        for (int e = 0; e < NE; e++) acc[e] += xv * srw[e * HDIM + h];
    }
#pragma unroll
    for (int off = 16; off > 0; off >>= 1) {
#pragma unroll
        for (int e = 0; e < NE; e++) acc[e] += __shfl_xor_sync(0xffffffffu, acc[e], off);
    }
    if (lane == 0) {
        float mx = acc[0];
#pragma unroll
        for (int e = 1; e < NE; e++) mx = fmaxf(mx, acc[e]);
        float p[NE], s = 0.0f;
#pragma unroll
        for (int e = 0; e < NE; e++) { p[e] = expf(acc[e] - mx); s += p[e]; }
        float inv = 1.0f / s;
#pragma unroll
        for (int e = 0; e < NE; e++) p[e] *= inv;
        int i1 = 0;
#pragma unroll
        for (int e = 1; e < NE; e++) if (p[e] > p[i1]) i1 = e;
        int i2 = (i1 == 0) ? 1 : 0;
#pragma unroll
        for (int e = 0; e < NE; e++) if (e != i1 && p[e] > p[i2]) i2 = e;
        g_topk_i[t * 2 + 0] = i1; g_topk_w[t * 2 + 0] = p[i1];
        g_topk_i[t * 2 + 1] = i2; g_topk_w[t * 2 + 1] = p[i2];
        atomicAdd(&g_counts[i1], 1);
        atomicAdd(&g_counts[i2], 1);
    }
}

__global__ void scan_kernel() {
    if (threadIdx.x == 0) {
        int o = 0;
        g_offsets[0] = 0;
        for (int e = 0; e < NE; e++) {
            g_cursor[e] = o;
            o += g_counts[e];
            g_offsets[e + 1] = o;
        }
    }
}

__global__ void scatter_kernel() {
    int t = blockIdx.x * 256 + threadIdx.x;
    if (t < TOK) {
#pragma unroll
        for (int s = 0; s < 2; s++) {
            int e = g_topk_i[t * 2 + s];
            int pos = atomicAdd(&g_cursor[e], 1);
            g_list[pos] = t * 2 + s;
        }
    }
}

// ---------------- grouped GEMM ----------------------------------------------
// Block tile 128x128x32, 256 threads, 2(M)x4(N) warps, warp tile 64x32 via
// m16n8k8 tf32 mma.sync. Double-buffered cp.async pipeline (2 stages).
// FFN1: A = gathered x rows -> gelu -> g_hid.
// FFN2: A = g_hid rows -> weighted -> g_contrib (per pair id, deterministic).
template <int KDIM_, int NDIM_, bool FFN1>
__global__ __launch_bounds__(256, 2) void moe_gemm(const float* __restrict__ x,
                                                   const float* __restrict__ W,
                                                   const float* __restrict__ bias) {
    constexpr int BK = 32;
    constexpr int AST = 36;    // 32+4 floats: 16B padding keeps cp.async alignment
    constexpr int BST = 136;   // 128+8 floats
    constexpr int ASZ = 128 * AST;  // 4608 floats / stage
    constexpr int BSZ = 32 * BST;   // 4352 floats / stage
    extern __shared__ float smem[];
    float* As = smem;              // [2][ASZ]
    float* Bs = smem + 2 * ASZ;    // [2][BSZ]

    int tid = threadIdx.x;
    int e = blockIdx.y >> 6;
    int rt = blockIdx.y & 63;
    int seg0 = g_offsets[e], seg1 = g_offsets[e + 1];
    int row0 = seg0 + rt * 128;
    if (row0 >= seg1) return;
    int n0 = blockIdx.x * 128;

    int warp = tid >> 5, lane = tid & 31;
    int wm = warp & 1, wn = warp >> 1;
    int group = lane >> 2, quad = lane & 3;

    // ---- A loader: 2 threads per row, 16 floats each (row fixed across K) ----
    int arow = tid >> 1;
    int acolf = (tid & 1) * 16;
    int gidx = row0 + arow;
    bool avalid = gidx < seg1;
    const float* asrc;
    if (FFN1) {
        int pair = avalid ? g_list[gidx] : 0;
        asrc = x + (size_t)(pair >> 1) * KDIM_ + acolf;
    } else {
        asrc = g_hid + (size_t)(avalid ? gidx : row0) * KDIM_ + acolf;
    }
    int abytes = avalid ? 16 : 0;
    uint32_t a_smem = (uint32_t)__cvta_generic_to_shared(As) + (uint32_t)(arow * AST + acolf) * 4u;

    // ---- B loader: 8 threads per row of 128, 16 floats each ----
    int brow = tid >> 3;
    int bcolf = (tid & 7) * 16;
    const float* bsrc = W + (size_t)e * KDIM_ * NDIM_ + (size_t)brow * NDIM_ + n0 + bcolf;
    uint32_t b_smem = (uint32_t)__cvta_generic_to_shared(Bs) + (uint32_t)(brow * BST + bcolf) * 4u;

    auto load_stage = [&](int stage, int k0) {
        uint32_t ad = a_smem + (uint32_t)(stage * ASZ) * 4u;
        const float* as = asrc + k0;
        cp16(ad +  0, as + 0, abytes);
        cp16(ad + 16, as + 4, abytes);
        cp16(ad + 32, as + 8, abytes);
        cp16(ad + 48, as + 12, abytes);
        uint32_t bd = b_smem + (uint32_t)(stage * BSZ) * 4u;
        const float* bs = bsrc + (size_t)k0 * NDIM_;
        cp16(bd +  0, bs + 0, 16);
        cp16(bd + 16, bs + 4, 16);
        cp16(bd + 32, bs + 8, 16);
        cp16(bd + 48, bs + 12, 16);
        asm volatile("cp.async.commit_group;");
    };

    float acc[4][4][4];
#pragma unroll
    for (int mi = 0; mi < 4; mi++)
#pragma unroll
        for (int ni = 0; ni < 4; ni++)
#pragma unroll
            for (int d = 0; d < 4; d++) acc[mi][ni][d] = 0.0f;

    constexpr int KT = KDIM_ / BK;
    load_stage(0, 0);

    for (int kt = 0; kt < KT; kt++) {
        int cur = kt & 1;
        if (kt + 1 < KT) {
            load_stage(cur ^ 1, (kt + 1) * BK);
            asm volatile("cp.async.wait_group 1;");
        } else {
            asm volatile("cp.async.wait_group 0;");
        }
        __syncthreads();

        const float* Acur = As + cur * ASZ;
        const float* Bcur = Bs + cur * BSZ;
#pragma unroll
        for (int ks = 0; ks < 4; ks++) {
            int kk = ks * 8;
            uint32_t af[4][4];
#pragma unroll
            for (int mi = 0; mi < 4; mi++) {
                const float* a0 = Acur + (wm * 64 + mi * 16 + group) * AST + kk + quad;
                af[mi][0] = f2tf32(a0[0]);
                af[mi][1] = f2tf32(a0[8 * AST]);
                af[mi][2] = f2tf32(a0[4]);
                af[mi][3] = f2tf32(a0[8 * AST + 4]);
            }
            uint32_t bf[4][2];
#pragma unroll
            for (int ni = 0; ni < 4; ni++) {
                const float* b0 = Bcur + (kk + quad) * BST + wn * 32 + ni * 8 + group;
                bf[ni][0] = f2tf32(b0[0]);
                bf[ni][1] = f2tf32(b0[4 * BST]);
            }
#pragma unroll
            for (int mi = 0; mi < 4; mi++)
#pragma unroll
                for (int ni = 0; ni < 4; ni++) mma_tf32(acc[mi][ni], af[mi], bf[ni]);
        }
        __syncthreads();
    }

    // ---- epilogue ----
#pragma unroll
    for (int mi = 0; mi < 4; mi++) {
#pragma unroll
        for (int half = 0; half < 2; half++) {
            int grow = row0 + wm * 64 + mi * 16 + group + half * 8;
            if (grow < seg1) {
                if (FFN1) {
#pragma unroll
                    for (int ni = 0; ni < 4; ni++) {
                        int col = n0 + wn * 32 + ni * 8 + quad * 2;
                        float v0 = acc[mi][ni][half * 2 + 0] + bias[(size_t)e * NDIM_ + col];
                        float v1 = acc[mi][ni][half * 2 + 1] + bias[(size_t)e * NDIM_ + col + 1];
                        v0 = gelu_exact(v0);
                        v1 = gelu_exact(v1);
                        *(float2*)(g_hid + (size_t)grow * NDIM_ + col) = make_float2(v0, v1);
                    }
                } else {
                    int pair = g_list[grow];
                    float wgt = g_topk_w[pair];
#pragma unroll
                    for (int ni = 0; ni < 4; ni++) {
                        int col = n0 + wn * 32 + ni * 8 + quad * 2;
                        float v0 = (acc[mi][ni][half * 2 + 0] + bias[(size_t)e * NDIM_ + col]) * wgt;
                        float v1 = (acc[mi][ni][half * 2 + 1] + bias[(size_t)e * NDIM_ + col + 1]) * wgt;
                        *(float2*)(g_contrib + (size_t)pair * NDIM_ + col) = make_float2(v0, v1);
                    }
                }
            }
        }
    }
}

// ---------------- combine ----------------------------------------------------
__global__ void combine_kernel(float* __restrict__ out) {
    constexpr int H4 = HDIM / 4;
    size_t i = (size_t)blockIdx.x * blockDim.x + threadIdx.x;
    if (i < (size_t)TOK * H4) {
        size_t t = i / H4, h4 = i % H4;
        const float4* c = (const float4*)g_contrib;
        float4 a = c[(t * 2) * H4 + h4];
        float4 b = c[(t * 2 + 1) * H4 + h4];
        float4 o = make_float4(a.x + b.x, a.y + b.y, a.z + b.z, a.w + b.w);
        ((float4*)out)[i] = o;
    }
}

// ---------------- launch ------------------------------------------------------
extern "C" void kernel_launch(void* const* d_in, const int* in_sizes, int n_in,
                              void* d_out, int out_size) {
    const float* x  = (const float*)d_in[0];
    const float* rw = (const float*)d_in[1];
    const float* w1 = (const float*)d_in[2];
    const float* b1 = (const float*)d_in[3];
    const float* w2 = (const float*)d_in[4];
    const float* b2 = (const float*)d_in[5];
    float* out = (float*)d_out;

    constexpr int SMEM_BYTES = (2 * 128 * 36 + 2 * 32 * 136) * 4;  // 71680
    cudaFuncSetAttribute(moe_gemm<HDIM, FDIM, true >,
                         cudaFuncAttributeMaxDynamicSharedMemorySize, SMEM_BYTES);
    cudaFuncSetAttribute(moe_gemm<FDIM, HDIM, false>,
                         cudaFuncAttributeMaxDynamicSharedMemorySize, SMEM_BYTES);

    reset_kernel<<<1, 32>>>();
    router_kernel<<<TOK / 8, 256>>>(x, rw);
    scan_kernel<<<1, 32>>>();
    scatter_kernel<<<TOK / 256, 256>>>();
    moe_gemm<HDIM, FDIM, true ><<<dim3(FDIM / 128, NE * 64), 256, SMEM_BYTES>>>(x, w1, b1);
    moe_gemm<FDIM, HDIM, false><<<dim3(HDIM / 128, NE * 64), 256, SMEM_BYTES>>>(x, w2, b2);
    combine_kernel<<<(TOK * HDIM / 4) / 256, 256>>>(out);
}

// round 4
// speedup vs baseline: 4.3447x; 3.1333x over previous
#include <cuda_runtime.h>
#include <cuda_fp16.h>
#include <cstdint>

#define TOK   8192
#define HDIM  1024
#define FDIM  4096
#define NE    8

// ---------------- scratch (static device globals) ---------------------------
__device__ int    g_counts[NE];
__device__ int    g_offsets[NE + 1];
__device__ int    g_cursor[NE];
__device__ int    g_topk_i[TOK * 2];
__device__ float  g_topk_w[TOK * 2];
__device__ int    g_list[TOK * 2];
__device__ __half g_xh[(size_t)TOK * HDIM];            // x in fp16
__device__ __half g_w1h[(size_t)NE * HDIM * FDIM];     // w1 in fp16
__device__ __half g_w2h[(size_t)NE * FDIM * HDIM];     // w2 in fp16
__device__ __half g_hidh[(size_t)TOK * 2 * FDIM];      // gelu(x@w1+b1) fp16
__device__ float  g_contrib[(size_t)TOK * 2 * HDIM];   // fp32 weighted expert out

// ---------------- PTX helpers ------------------------------------------------
__device__ __forceinline__ uint32_t smem_u32(const void* p) {
    uint32_t a;
    asm("{ .reg .u64 t; cvta.to.shared.u64 t, %1; cvt.u32.u64 %0, t; }" : "=r"(a) : "l"(p));
    return a;
}
__device__ __forceinline__ void cp16(uint32_t dst, const void* src, int bytes) {
    asm volatile("cp.async.cg.shared.global [%0], [%1], 16, %2;"
                 :: "r"(dst), "l"(src), "r"(bytes));
}
__device__ __forceinline__ void ldsm4(uint32_t* r, uint32_t addr) {
    asm volatile("ldmatrix.sync.aligned.m8n8.x4.shared.b16 {%0,%1,%2,%3}, [%4];"
                 : "=r"(r[0]), "=r"(r[1]), "=r"(r[2]), "=r"(r[3]) : "r"(addr));
}
__device__ __forceinline__ void ldsm4t(uint32_t* r, uint32_t addr) {
    asm volatile("ldmatrix.sync.aligned.m8n8.x4.trans.shared.b16 {%0,%1,%2,%3}, [%4];"
                 : "=r"(r[0]), "=r"(r[1]), "=r"(r[2]), "=r"(r[3]) : "r"(addr));
}
__device__ __forceinline__ void mma_f16(float* d, const uint32_t* a, const uint32_t* b) {
    asm volatile(
        "mma.sync.aligned.m16n8k16.row.col.f32.f16.f16.f32 "
        "{%0,%1,%2,%3}, {%4,%5,%6,%7}, {%8,%9}, {%0,%1,%2,%3};"
        : "+f"(d[0]), "+f"(d[1]), "+f"(d[2]), "+f"(d[3])
        : "r"(a[0]), "r"(a[1]), "r"(a[2]), "r"(a[3]), "r"(b[0]), "r"(b[1]));
}
__device__ __forceinline__ float gelu_exact(float v) {
    return 0.5f * v * (1.0f + erff(v * 0.70710678118654752f));
}

// ---------------- small kernels ----------------------------------------------
__global__ void reset_kernel() {
    if (threadIdx.x < NE) g_counts[threadIdx.x] = 0;
}

// fp32 -> fp16, 8 elems per thread
__global__ void cvt_half_kernel(const float* __restrict__ src, __half* __restrict__ dst,
                                size_t n8) {
    size_t i = (size_t)blockIdx.x * blockDim.x + threadIdx.x;
    if (i < n8) {
        float4 v0 = ((const float4*)src)[i * 2];
        float4 v1 = ((const float4*)src)[i * 2 + 1];
        __half2 h[4];
        h[0] = __floats2half2_rn(v0.x, v0.y);
        h[1] = __floats2half2_rn(v0.z, v0.w);
        h[2] = __floats2half2_rn(v1.x, v1.y);
        h[3] = __floats2half2_rn(v1.z, v1.w);
        ((uint4*)dst)[i] = *(uint4*)h;
    }
}

__global__ void router_kernel(const float* __restrict__ x, const float* __restrict__ rw) {
    __shared__ float srw[NE * HDIM];
    int tid = threadIdx.x;
    for (int i = tid; i < NE * HDIM; i += 256) srw[i] = rw[i];
    __syncthreads();
    int warp = tid >> 5, lane = tid & 31;
    int t = blockIdx.x * 8 + warp;
    if (t >= TOK) return;
    const float* xr = x + (size_t)t * HDIM;
    float acc[NE];
#pragma unroll
    for (int e = 0; e < NE; e++) acc[e] = 0.0f;
    for (int h = lane; h < HDIM; h += 32) {
        float xv = xr[h];
#pragma unroll
        for (int e = 0; e < NE; e++) acc[e] += xv * srw[e * HDIM + h];
    }
#pragma unroll
    for (int off = 16; off > 0; off >>= 1)
#pragma unroll
        for (int e = 0; e < NE; e++) acc[e] += __shfl_xor_sync(0xffffffffu, acc[e], off);
    if (lane == 0) {
        float mx = acc[0];
#pragma unroll
        for (int e = 1; e < NE; e++) mx = fmaxf(mx, acc[e]);
        float p[NE], s = 0.0f;
#pragma unroll
        for (int e = 0; e < NE; e++) { p[e] = expf(acc[e] - mx); s += p[e]; }
        float inv = 1.0f / s;
#pragma unroll
        for (int e = 0; e < NE; e++) p[e] *= inv;
        int i1 = 0;
#pragma unroll
        for (int e = 1; e < NE; e++) if (p[e] > p[i1]) i1 = e;
        int i2 = (i1 == 0) ? 1 : 0;
#pragma unroll
        for (int e = 0; e < NE; e++) if (e != i1 && p[e] > p[i2]) i2 = e;
        g_topk_i[t * 2 + 0] = i1; g_topk_w[t * 2 + 0] = p[i1];
        g_topk_i[t * 2 + 1] = i2; g_topk_w[t * 2 + 1] = p[i2];
        atomicAdd(&g_counts[i1], 1);
        atomicAdd(&g_counts[i2], 1);
    }
}

__global__ void scan_kernel() {
    if (threadIdx.x == 0) {
        int o = 0;
        g_offsets[0] = 0;
        for (int e = 0; e < NE; e++) {
            g_cursor[e] = o;
            o += g_counts[e];
            g_offsets[e + 1] = o;
        }
    }
}

__global__ void scatter_kernel() {
    int t = blockIdx.x * 256 + threadIdx.x;
    if (t < TOK) {
#pragma unroll
        for (int s = 0; s < 2; s++) {
            int e = g_topk_i[t * 2 + s];
            int pos = atomicAdd(&g_cursor[e], 1);
            g_list[pos] = t * 2 + s;
        }
    }
}

// ---------------- fp16 grouped GEMM (mma.sync m16n8k16 + ldmatrix) -----------
// Tile 128x128, BK=64 (fp16), 128 threads = 4 warps in 2(M)x2(N), warp tile
// 64x64. 3-stage cp.async pipeline, ONE __syncthreads per K-tile.
// SMEM stage (32KB): A [128 rows][64 halves] swizzled, B [64 k-rows][128 halves].
template <int KD, int ND, bool FFN1>
__global__ void __launch_bounds__(128, 2)
moe_gemm_h(const __half* __restrict__ Ah, const __half* __restrict__ Wh,
           const float* __restrict__ bias) {
    extern __shared__ char smem[];
    uint32_t smb = smem_u32(smem);

    int tid = threadIdx.x;
    int warp = tid >> 5, lane = tid & 31;
    int wm = warp & 1, wn = warp >> 1;
    int l15 = lane & 15, hi = lane >> 4;

    int e = blockIdx.y >> 6;
    int rt = blockIdx.y & 63;
    int seg0 = g_offsets[e], seg1 = g_offsets[e + 1];
    int row0 = seg0 + rt * 128;
    if (row0 >= seg1) return;
    int n0 = blockIdx.x * 128;

    // ---- A loader: 8 chunks/thread (row = idx>>3, c = idx&7), 16B chunks ----
    const __half* a_src[8];
    int a_bytes[8];
#pragma unroll
    for (int j = 0; j < 8; j++) {
        int idx = tid + 128 * j;
        int row = idx >> 3, c = idx & 7;
        int grow = row0 + row;
        bool v = grow < seg1;
        if (FFN1) {
            int pair = v ? g_list[grow] : 0;
            a_src[j] = Ah + (size_t)(pair >> 1) * KD + c * 8;
        } else {
            a_src[j] = Ah + (size_t)(v ? grow : row0) * KD + c * 8;
        }
        a_bytes[j] = v ? 16 : 0;
    }
    const __half* wbase = Wh + (size_t)e * KD * ND + n0;

    auto load_stage = [&](int s, int kt) {
        int k0 = kt * 64;
        uint32_t base = smb + s * 32768;
#pragma unroll
        for (int j = 0; j < 8; j++) {
            int idx = tid + 128 * j;
            int row = idx >> 3, c = idx & 7;
            uint32_t off = (uint32_t)row * 128 + (uint32_t)((c ^ (row & 7)) << 4);
            cp16(base + off, a_src[j] + k0, a_bytes[j]);
        }
#pragma unroll
        for (int j = 0; j < 8; j++) {
            int idx = tid + 128 * j;
            int k = idx >> 4, c = idx & 15;
            uint32_t off = 16384u + (uint32_t)k * 256 + (uint32_t)((c ^ (k & 7)) << 4);
            cp16(base + off, wbase + (size_t)(k0 + k) * ND + c * 8, 16);
        }
        asm volatile("cp.async.commit_group;");
    };

    float acc[4][8][4];
#pragma unroll
    for (int mi = 0; mi < 4; mi++)
#pragma unroll
        for (int ni = 0; ni < 8; ni++)
#pragma unroll
            for (int d = 0; d < 4; d++) acc[mi][ni][d] = 0.0f;

    constexpr int KT = KD / 64;
    load_stage(0, 0);
    load_stage(1, 1);

    for (int kt = 0; kt < KT; kt++) {
        if (kt + 1 < KT) asm volatile("cp.async.wait_group 1;");
        else             asm volatile("cp.async.wait_group 0;");
        __syncthreads();
        if (kt + 2 < KT) load_stage((kt + 2) % 3, kt + 2);

        uint32_t abase = smb + (kt % 3) * 32768;
        uint32_t bbase = abase + 16384;
#pragma unroll
        for (int ks = 0; ks < 4; ks++) {
            uint32_t a[4][4];
#pragma unroll
            for (int mi = 0; mi < 4; mi++) {
                int row = wm * 64 + mi * 16 + l15;
                uint32_t addr = abase + (uint32_t)row * 128 +
                                (uint32_t)(((ks * 2 + hi) ^ (row & 7)) << 4);
                ldsm4(a[mi], addr);
            }
            uint32_t b[4][4];
#pragma unroll
            for (int np = 0; np < 4; np++) {
                int krow = ks * 16 + l15;
                int c = wn * 8 + np * 2 + hi;
                uint32_t addr = bbase + (uint32_t)krow * 256 +
                                (uint32_t)((c ^ (krow & 7)) << 4);
                ldsm4t(b[np], addr);
            }
#pragma unroll
            for (int mi = 0; mi < 4; mi++)
#pragma unroll
                for (int np = 0; np < 4; np++) {
                    mma_f16(acc[mi][np * 2 + 0], a[mi], b[np] + 0);
                    mma_f16(acc[mi][np * 2 + 1], a[mi], b[np] + 2);
                }
        }
    }

    // ---- epilogue (register accumulators) ----
    int r4 = lane >> 2, c2 = (lane & 3) * 2;
#pragma unroll
    for (int mi = 0; mi < 4; mi++) {
#pragma unroll
        for (int h = 0; h < 2; h++) {
            int grow = row0 + wm * 64 + mi * 16 + r4 + h * 8;
            if (grow < seg1) {
                if (FFN1) {
                    __half* orow = g_hidh + (size_t)grow * ND;
#pragma unroll
                    for (int ni = 0; ni < 8; ni++) {
                        int col = n0 + wn * 64 + ni * 8 + c2;
                        float2 bv = *(const float2*)(bias + (size_t)e * ND + col);
                        float v0 = gelu_exact(acc[mi][ni][h * 2 + 0] + bv.x);
                        float v1 = gelu_exact(acc[mi][ni][h * 2 + 1] + bv.y);
                        *(__half2*)(orow + col) = __floats2half2_rn(v0, v1);
                    }
                } else {
                    int pair = g_list[grow];
                    float wgt = g_topk_w[pair];
                    float* orow = g_contrib + (size_t)pair * ND;
#pragma unroll
                    for (int ni = 0; ni < 8; ni++) {
                        int col = n0 + wn * 64 + ni * 8 + c2;
                        float2 bv = *(const float2*)(bias + (size_t)e * ND + col);
                        float v0 = (acc[mi][ni][h * 2 + 0] + bv.x) * wgt;
                        float v1 = (acc[mi][ni][h * 2 + 1] + bv.y) * wgt;
                        *(float2*)(orow + col) = make_float2(v0, v1);
                    }
                }
            }
        }
    }
}

// ---------------- combine -----------------------------------------------------
__global__ void combine_kernel(float* __restrict__ out) {
    constexpr int H4 = HDIM / 4;
    size_t i = (size_t)blockIdx.x * blockDim.x + threadIdx.x;
    if (i < (size_t)TOK * H4) {
        size_t t = i / H4, h4 = i % H4;
        const float4* c = (const float4*)g_contrib;
        float4 a = c[(t * 2) * H4 + h4];
        float4 b = c[(t * 2 + 1) * H4 + h4];
        ((float4*)out)[i] = make_float4(a.x + b.x, a.y + b.y, a.z + b.z, a.w + b.w);
    }
}

// ---------------- launch --------------------------------------------------------
extern "C" void kernel_launch(void* const* d_in, const int* in_sizes, int n_in,
                              void* d_out, int out_size) {
    const float* x  = (const float*)d_in[0];
    const float* rw = (const float*)d_in[1];
    const float* w1 = (const float*)d_in[2];
    const float* b1 = (const float*)d_in[3];
    const float* w2 = (const float*)d_in[4];
    const float* b2 = (const float*)d_in[5];
    float* out = (float*)d_out;

    __half* xh;  cudaGetSymbolAddress((void**)&xh,  g_xh);
    __half* w1h; cudaGetSymbolAddress((void**)&w1h, g_w1h);
    __half* w2h; cudaGetSymbolAddress((void**)&w2h, g_w2h);
    __half* hid; cudaGetSymbolAddress((void**)&hid, g_hidh);

    constexpr int SMEM_BYTES = 3 * 32768;  // 98304
    cudaFuncSetAttribute(moe_gemm_h<HDIM, FDIM, true >,
                         cudaFuncAttributeMaxDynamicSharedMemorySize, SMEM_BYTES);
    cudaFuncSetAttribute(moe_gemm_h<FDIM, HDIM, false>,
                         cudaFuncAttributeMaxDynamicSharedMemorySize, SMEM_BYTES);

    reset_kernel<<<1, 32>>>();
    router_kernel<<<TOK / 8, 256>>>(x, rw);
    scan_kernel<<<1, 32>>>();
    scatter_kernel<<<TOK / 256, 256>>>();

    size_t nx  = (size_t)TOK * HDIM / 8;
    size_t nw1 = (size_t)NE * HDIM * FDIM / 8;
    size_t nw2 = (size_t)NE * FDIM * HDIM / 8;
    cvt_half_kernel<<<(int)((nx  + 255) / 256), 256>>>(x,  xh,  nx);
    cvt_half_kernel<<<(int)((nw1 + 255) / 256), 256>>>(w1, w1h, nw1);
    cvt_half_kernel<<<(int)((nw2 + 255) / 256), 256>>>(w2, w2h, nw2);

    moe_gemm_h<HDIM, FDIM, true ><<<dim3(FDIM / 128, NE * 64), 128, SMEM_BYTES>>>(xh,  w1h, b1);
    moe_gemm_h<FDIM, HDIM, false><<<dim3(HDIM / 128, NE * 64), 128, SMEM_BYTES>>>(hid, w2h, b2);
    combine_kernel<<<(TOK * HDIM / 4) / 256, 256>>>(out);
}